// round 15
// baseline (speedup 1.0000x reference)
#include <cuda_runtime.h>
#include <cstdint>

// ---------------------------------------------------------------------------
// QuantTrinaryFCMNIST — Round 15: R13 base + integer-threshold ternarize.
//   gemm1 last CTA binary-searches per-column integer thresholds (bit-exact
//   vs the float fma path) + sign-folds W2 -> g_W2adj.
//   gemm2 inner loop: pure smem loads + integer compares + dp4a.
//   quant_x: 2 float4 / thread (MLP 2).
// All cross-batch stats exact integer sums -> deterministic.
// ---------------------------------------------------------------------------

#define B_ROWS 16384
#define K1     784          // 12 chunks of 64B + 1 tail of 16B
#define N1     1024
#define K2     1024
#define N2     10
#define OUT_N  (B_ROWS * N2)
#define HBINS  2049         // C2 in [-1024, 1024]

typedef unsigned int uint;
typedef unsigned long long ull;

// ------------------------- scratch (device globals) ------------------------
__device__ __align__(256) int8_t g_Aq [(size_t)B_ROWS * K1];
__device__ __align__(256) int8_t g_W1q[(size_t)N1 * K1];
__device__ __align__(256) int8_t g_W2q[N2 * K2];
__device__ __align__(256) int8_t g_W2adj[N2 * K2];   // sign-folded W2
__device__ __align__(256) short  g_C1s[(size_t)B_ROWS * N1];
__device__ __align__(16)  short  g_thrH[N1];         // tern thresholds
__device__ __align__(16)  short  g_thrL[N1];
__device__ int    g_C2 [OUT_N];
__device__ int    g_sum1[N1];
__device__ ull    g_sq1 [N1];
__device__ int    g_sum2p[64][N2];     // spread partials
__device__ int    g_sq2p [64][N2];
__device__ float  g_scale2[N2], g_shift2[N2];
__device__ int    g_hist[N2 * HBINS];
__device__ float  g_tn_mean, g_tn_inv;
__device__ int    g_t1a[64], g_t1m;    // gemm1 two-level ticket
__device__ int    g_t2a[64], g_t2m;    // gemm2 two-level ticket

// exact: clip(round-half-even(y),-1,1) == (y>0.5)-(y<-0.5) for all floats
__device__ __forceinline__ int terni(float y) {
    return (int)(y > 0.5f) - (int)(y < -0.5f);
}

__device__ __forceinline__ uint smem_u32(const void* p) {
    uint a;
    asm("{ .reg .u64 t; cvta.to.shared.u64 t, %1; cvt.u32.u64 %0, t; }"
        : "=r"(a) : "l"(p));
    return a;
}
#define CP_ASYNC16(dst, src) \
    asm volatile("cp.async.ca.shared.global [%0], [%1], 16;" \
                 :: "r"(dst), "l"(src) : "memory")
#define CP_COMMIT() asm volatile("cp.async.commit_group;" ::: "memory")
#define CP_WAIT0()  asm volatile("cp.async.wait_group 0;" ::: "memory")

// --------------------------- quantize kernels ------------------------------
// tern(2x-1): 2x-1>0.5 <=> x>0.75 ; 2x-1<-0.5 <=> x<0.25. 2 float4/thread.
__global__ void __launch_bounds__(256) quant_x_kernel(const float* __restrict__ x) {
    int i0 = blockIdx.x * 512 + threadIdx.x;
    float4 fa = reinterpret_cast<const float4*>(x)[i0];
    float4 fb = reinterpret_cast<const float4*>(x)[i0 + 256];
    char4 va, vb;
    va.x = (int8_t)((fa.x > 0.75f) - (fa.x < 0.25f));
    va.y = (int8_t)((fa.y > 0.75f) - (fa.y < 0.25f));
    va.z = (int8_t)((fa.z > 0.75f) - (fa.z < 0.25f));
    va.w = (int8_t)((fa.w > 0.75f) - (fa.w < 0.25f));
    vb.x = (int8_t)((fb.x > 0.75f) - (fb.x < 0.25f));
    vb.y = (int8_t)((fb.y > 0.75f) - (fb.y < 0.25f));
    vb.z = (int8_t)((fb.z > 0.75f) - (fb.z < 0.25f));
    vb.w = (int8_t)((fb.w > 0.75f) - (fb.w < 0.25f));
    reinterpret_cast<char4*>(g_Aq)[i0]       = va;
    reinterpret_cast<char4*>(g_Aq)[i0 + 256] = vb;
}

// W1 (784 float4-blocks) + W2 (10 blocks) + all zeroing, one kernel
__global__ void __launch_bounds__(256) quant_w_kernel(const float* __restrict__ w1,
                                                      const float* __restrict__ w2) {
    const int b = blockIdx.x, t = threadIdx.x;
    if (b < 784) {
        int idx = b * 256 + t;
        float4 f = reinterpret_cast<const float4*>(w1)[idx];
        char4 v;
        v.x = (int8_t)terni(f.x);
        v.y = (int8_t)terni(f.y);
        v.z = (int8_t)terni(f.z);
        v.w = (int8_t)terni(f.w);
        reinterpret_cast<char4*>(g_W1q)[idx] = v;
    } else {
        int idx = (b - 784) * 256 + t;
        if (idx < N2 * K2 / 4) {
            float4 f = reinterpret_cast<const float4*>(w2)[idx];
            char4 v;
            v.x = (int8_t)terni(f.x);
            v.y = (int8_t)terni(f.y);
            v.z = (int8_t)terni(f.z);
            v.w = (int8_t)terni(f.w);
            reinterpret_cast<char4*>(g_W2q)[idx] = v;
        }
    }
    if (b < 81) {                       // zero histogram (10*2049 ints)
        int i = b * 256 + t;
        if (i < N2 * HBINS) g_hist[i] = 0;
    } else if (b == 100) {
        for (int j = t; j < N1; j += 256) g_sum1[j] = 0;
    } else if (b == 101) {
        for (int j = t; j < N1; j += 256) g_sq1[j] = 0ull;
    } else if (b == 102) {
        for (int i = t; i < 64 * N2; i += 256) {
            (&g_sum2p[0][0])[i] = 0;
            (&g_sq2p[0][0])[i]  = 0;
        }
        if (t < 64) { g_t1a[t] = 0; g_t2a[t] = 0; }
        if (t == 64) { g_t1m = 0; g_t2m = 0; }
    }
}

// ------------------------------- GEMM1 (dp4a) -------------------------------
// Core UNCHANGED (at the rt=2 dp4a roofline). Tile 128x128, BK=64 + 16B tail,
// 256 threads, 8x8/thread, double-buffered, one sync/chunk.
// Last CTA: per-column integer tern thresholds (bit-exact binary search over
// the float fma expression) + sign-folded W2adj.
#define SP 132

__global__ void __launch_bounds__(256, 2)
gemm1_kernel(const float* __restrict__ gamma1, const float* __restrict__ beta1) {
    __shared__ __align__(16) uint As[2][16][SP];
    __shared__ __align__(16) uint Bs[2][16][SP];
    __shared__ int s_sum[128];
    __shared__ int s_sq [128];
    __shared__ int s_last;
    __shared__ char s_flip[N1];

    const int t  = threadIdx.x;
    const int ty = t >> 4, tx = t & 15;
    const int m0 = blockIdx.x * 128;
    const int n0 = blockIdx.y * 128;

    int acc[8][8];
#pragma unroll
    for (int i = 0; i < 8; i++)
#pragma unroll
        for (int j = 0; j < 8; j++) acc[i][j] = 0;

    const int prow = t >> 2, pseg = t & 3;
    const int8_t* Ag0 = g_Aq  + (size_t)(m0 + prow)      * K1 + pseg * 16;
    const int8_t* Ag1 = g_Aq  + (size_t)(m0 + prow + 64) * K1 + pseg * 16;
    const int8_t* Bg0 = g_W1q + (size_t)(n0 + prow)      * K1 + pseg * 16;
    const int8_t* Bg1 = g_W1q + (size_t)(n0 + prow + 64) * K1 + pseg * 16;

    uint4 ra0, ra1, rb0, rb1;

    ra0 = *reinterpret_cast<const uint4*>(Ag0);
    ra1 = *reinterpret_cast<const uint4*>(Ag1);
    rb0 = *reinterpret_cast<const uint4*>(Bg0);
    rb1 = *reinterpret_cast<const uint4*>(Bg1);
#pragma unroll
    for (int w = 0; w < 4; w++) {
        As[0][pseg * 4 + w][prow]      = (&ra0.x)[w];
        As[0][pseg * 4 + w][prow + 64] = (&ra1.x)[w];
        Bs[0][pseg * 4 + w][prow]      = (&rb0.x)[w];
        Bs[0][pseg * 4 + w][prow + 64] = (&rb1.x)[w];
    }
    __syncthreads();

    for (int kc = 0; kc < 12; kc++) {
        const int buf = kc & 1;
        const bool next_full = (kc + 1 < 12);
        if (next_full) {
            ra0 = *reinterpret_cast<const uint4*>(Ag0 + (kc + 1) * 64);
            ra1 = *reinterpret_cast<const uint4*>(Ag1 + (kc + 1) * 64);
            rb0 = *reinterpret_cast<const uint4*>(Bg0 + (kc + 1) * 64);
            rb1 = *reinterpret_cast<const uint4*>(Bg1 + (kc + 1) * 64);
        } else if (pseg == 0) {          // tail: bytes 768..783
            ra0 = *reinterpret_cast<const uint4*>(Ag0 + 768);
            ra1 = *reinterpret_cast<const uint4*>(Ag1 + 768);
            rb0 = *reinterpret_cast<const uint4*>(Bg0 + 768);
            rb1 = *reinterpret_cast<const uint4*>(Bg1 + 768);
        }

#pragma unroll
        for (int kk = 0; kk < 16; kk++) {
            uint4 a0 = *reinterpret_cast<const uint4*>(&As[buf][kk][ty * 8]);
            uint4 a1 = *reinterpret_cast<const uint4*>(&As[buf][kk][ty * 8 + 4]);
            uint4 b0 = *reinterpret_cast<const uint4*>(&Bs[buf][kk][tx * 8]);
            uint4 b1 = *reinterpret_cast<const uint4*>(&Bs[buf][kk][tx * 8 + 4]);
            int a[8] = {(int)a0.x, (int)a0.y, (int)a0.z, (int)a0.w,
                        (int)a1.x, (int)a1.y, (int)a1.z, (int)a1.w};
            int b[8] = {(int)b0.x, (int)b0.y, (int)b0.z, (int)b0.w,
                        (int)b1.x, (int)b1.y, (int)b1.z, (int)b1.w};
#pragma unroll
            for (int i = 0; i < 8; i++)
#pragma unroll
                for (int j = 0; j < 8; j++)
                    acc[i][j] = __dp4a(a[i], b[j], acc[i][j]);
        }

        const int nb = buf ^ 1;
        if (next_full) {
#pragma unroll
            for (int w = 0; w < 4; w++) {
                As[nb][pseg * 4 + w][prow]      = (&ra0.x)[w];
                As[nb][pseg * 4 + w][prow + 64] = (&ra1.x)[w];
                Bs[nb][pseg * 4 + w][prow]      = (&rb0.x)[w];
                Bs[nb][pseg * 4 + w][prow + 64] = (&rb1.x)[w];
            }
        } else if (pseg == 0) {
#pragma unroll
            for (int w = 0; w < 4; w++) {
                As[nb][w][prow]      = (&ra0.x)[w];
                As[nb][w][prow + 64] = (&ra1.x)[w];
                Bs[nb][w][prow]      = (&rb0.x)[w];
                Bs[nb][w][prow + 64] = (&rb1.x)[w];
            }
        }
        __syncthreads();
    }

    // tail chunk (4 kwords) sits in buffer 0
#pragma unroll
    for (int kk = 0; kk < 4; kk++) {
        uint4 a0 = *reinterpret_cast<const uint4*>(&As[0][kk][ty * 8]);
        uint4 a1 = *reinterpret_cast<const uint4*>(&As[0][kk][ty * 8 + 4]);
        uint4 b0 = *reinterpret_cast<const uint4*>(&Bs[0][kk][tx * 8]);
        uint4 b1 = *reinterpret_cast<const uint4*>(&Bs[0][kk][tx * 8 + 4]);
        int a[8] = {(int)a0.x, (int)a0.y, (int)a0.z, (int)a0.w,
                    (int)a1.x, (int)a1.y, (int)a1.z, (int)a1.w};
        int b[8] = {(int)b0.x, (int)b0.y, (int)b0.z, (int)b0.w,
                    (int)b1.x, (int)b1.y, (int)b1.z, (int)b1.w};
#pragma unroll
        for (int i = 0; i < 8; i++)
#pragma unroll
            for (int j = 0; j < 8; j++)
                acc[i][j] = __dp4a(a[i], b[j], acc[i][j]);
    }

    // ------------- epilogue: int16 C1 + fused exact BN1 stats -------------
    if (t < 128) { s_sum[t] = 0; s_sq[t] = 0; }
    __syncthreads();

#pragma unroll
    for (int i = 0; i < 8; i++) {
        const int row = m0 + ty * 8 + i;
        uint u0 = ((uint)acc[i][0] & 0xffffu) | ((uint)acc[i][1] << 16);
        uint u1 = ((uint)acc[i][2] & 0xffffu) | ((uint)acc[i][3] << 16);
        uint u2 = ((uint)acc[i][4] & 0xffffu) | ((uint)acc[i][5] << 16);
        uint u3 = ((uint)acc[i][6] & 0xffffu) | ((uint)acc[i][7] << 16);
        *reinterpret_cast<uint4*>((char*)g_C1s + (size_t)row * 2048 + (n0 + tx * 8) * 2) =
            make_uint4(u0, u1, u2, u3);
    }

#pragma unroll
    for (int j = 0; j < 8; j++) {
        int s = 0, q = 0;
#pragma unroll
        for (int i = 0; i < 8; i++) { s += acc[i][j]; q += acc[i][j] * acc[i][j]; }
        atomicAdd(&s_sum[tx * 8 + j], s);
        atomicAdd(&s_sq [tx * 8 + j], q);
    }
    __syncthreads();
    if (t < 128) {
        atomicAdd(&g_sum1[n0 + t], s_sum[t]);
        atomicAdd(&g_sq1 [n0 + t], (ull)(uint)s_sq[t]);
    }

    // ---- two-level ticket; last CTA computes thresholds + W2adj once ----
    __threadfence();
    __syncthreads();
    if (t == 0) {
        s_last = 0;
        const int slot = (blockIdx.y * 128 + blockIdx.x) & 63;
        if (atomicAdd(&g_t1a[slot], 1) == 15) {
            if (atomicAdd(&g_t1m, 1) == 63) s_last = 1;
        }
    }
    __syncthreads();
    if (s_last) {
        for (int j = t; j < N1; j += 256) {
            double mean = (double)g_sum1[j] * (1.0 / 16384.0);
            double var  = (double)g_sq1[j]  * (1.0 / 16384.0) - mean * mean;
            float  sc   = gamma1[j] * (float)(1.0 / sqrt(var + 1e-5));
            float  sf   = beta1[j] - (float)mean * sc;
            float  as   = sc;
            int flip = 0;
            if (as < 0.f) { as = -as; flip = 1; }
            int hi, lo;
            if (as == 0.f) {
                int tv = (sf > 0.5f) - (sf < -0.5f);
                if (tv > 0)       { hi = -1000; lo = -1000; }
                else if (tv == 0) { hi =  1000; lo = -1000; }
                else              { hi =  1000; lo =  1000; }
                flip = 0;
            } else {
                // terni(fmaf(d,as,sf)) over d in [-784,784], monotone in d
                int a = -785, b = 784;          // hi: max d with y <= 0.5f
                while (a < b) {
                    int m = (a + b + 1) >> 1;
                    if (fmaf((float)m, as, sf) <= 0.5f) a = m; else b = m - 1;
                }
                int HI = a;
                a = -784; b = 785;              // lo: min d with y >= -0.5f
                while (a < b) {
                    int m = (a + b) >> 1;
                    if (fmaf((float)m, as, sf) >= -0.5f) b = m; else a = m + 1;
                }
                int LO = a;
                if (!flip) { hi = HI; lo = LO; }
                else       { hi = -LO; lo = -HI; }   // tern = -[(c>hi)-(c<lo)]
            }
            g_thrH[j] = (short)hi;
            g_thrL[j] = (short)lo;
            s_flip[j] = (char)flip;
        }
        __syncthreads();
        for (int i = t; i < N2 * K2; i += 256) {   // sign-folded W2
            int k = i & 1023;
            int8_t w = g_W2q[i];
            g_W2adj[i] = s_flip[k] ? (int8_t)(-w) : w;
        }
    }
}

// ------------------------------- GEMM2 --------------------------------------
// Fused: t = (c>hi)-(c<lo) integer ternarize; C2 = t @ W2adj^T; C2 histogram;
// BN2 stats via 64-slot spread partials. All inner-loop operands in smem
// (C1 tile, W2adj, thresholds staged via cp.async). Two-level ticket;
// last CTA: slot-reduce bn2 params + tern counts (hist) + tensornorm consts.
__global__ void __launch_bounds__(256, 3)
gemm2_kernel(const float* __restrict__ gamma2, const float* __restrict__ beta2) {
    __shared__ __align__(16) short c1s[16 * K2];     // 32KB
    __shared__ __align__(16) uint2 w2v[N2 * 128];    // 10KB, [j][idx]
    __shared__ __align__(16) short thrH[K2];         // 2KB
    __shared__ __align__(16) short thrL[K2];         // 2KB
    __shared__ int   bsum[N2], bsq[N2];
    __shared__ int   s_last;
    __shared__ float sc2[N2], sh2[N2];
    __shared__ int   cpn[2];

    const int t = threadIdx.x;

    // ---- stage C1 tile + W2adj + thresholds via cp.async ----
    {
        const uint sc1 = smem_u32(c1s);
        const char* gsrc = (const char*)(g_C1s + (size_t)blockIdx.x * 16 * K2);
#pragma unroll
        for (int i = 0; i < 8; i++) {               // 2048 x 16B = 32KB
            int off = (i * 256 + t) * 16;
            CP_ASYNC16(sc1 + off, gsrc + off);
        }
        const uint sw = smem_u32(w2v);
        const char* gw = (const char*)g_W2adj;
        for (int i = t; i < 640; i += 256)           // 10KB
            CP_ASYNC16(sw + i * 16, gw + i * 16);
        if (t < 128)
            CP_ASYNC16(smem_u32(thrH) + t * 16, (const char*)g_thrH + t * 16);
        else
            CP_ASYNC16(smem_u32(thrL) + (t - 128) * 16,
                       (const char*)g_thrL + (t - 128) * 16);
        CP_COMMIT();
    }
    if (t < N2) { bsum[t] = 0; bsq[t] = 0; }
    CP_WAIT0();
    __syncthreads();

    const int warp = t >> 5, lane = t & 31;
    const int row0 = blockIdx.x * 16 + warp * 2;
    const int rloc = warp * 2;

    int acc0[N2], acc1[N2];
#pragma unroll
    for (int j = 0; j < N2; j++) { acc0[j] = 0; acc1[j] = 0; }

#pragma unroll
    for (int it = 0; it < 4; it++) {
        const int idx = it * 32 + lane;
        // row-invariant operands, all from smem
        short4 h0 = *reinterpret_cast<const short4*>(&thrH[idx * 8]);
        short4 h1 = *reinterpret_cast<const short4*>(&thrH[idx * 8 + 4]);
        short4 l0 = *reinterpret_cast<const short4*>(&thrL[idx * 8]);
        short4 l1 = *reinterpret_cast<const short4*>(&thrL[idx * 8 + 4]);
        uint2 w[N2];
#pragma unroll
        for (int j = 0; j < N2; j++) w[j] = w2v[j * 128 + idx];

#pragma unroll
        for (int r = 0; r < 2; r++) {
            const short4* cp = reinterpret_cast<const short4*>(
                c1s + (rloc + r) * K2 + idx * 8);
            short4 c0 = cp[0];
            short4 c1 = cp[1];
            int t0 = (c0.x > h0.x) - (c0.x < l0.x);
            int t1 = (c0.y > h0.y) - (c0.y < l0.y);
            int t2 = (c0.z > h0.z) - (c0.z < l0.z);
            int t3 = (c0.w > h0.w) - (c0.w < l0.w);
            int t4 = (c1.x > h1.x) - (c1.x < l1.x);
            int t5 = (c1.y > h1.y) - (c1.y < l1.y);
            int t6 = (c1.z > h1.z) - (c1.z < l1.z);
            int t7 = (c1.w > h1.w) - (c1.w < l1.w);
            uint p0 = (uint)(t0 & 0xff) | ((uint)(t1 & 0xff) << 8) |
                      ((uint)(t2 & 0xff) << 16) | ((uint)(t3 & 0xff) << 24);
            uint p1 = (uint)(t4 & 0xff) | ((uint)(t5 & 0xff) << 8) |
                      ((uint)(t6 & 0xff) << 16) | ((uint)(t7 & 0xff) << 24);
            if (r == 0) {
#pragma unroll
                for (int j = 0; j < N2; j++) {
                    acc0[j] = __dp4a((int)p0, (int)w[j].x, acc0[j]);
                    acc0[j] = __dp4a((int)p1, (int)w[j].y, acc0[j]);
                }
            } else {
#pragma unroll
                for (int j = 0; j < N2; j++) {
                    acc1[j] = __dp4a((int)p0, (int)w[j].x, acc1[j]);
                    acc1[j] = __dp4a((int)p1, (int)w[j].y, acc1[j]);
                }
            }
        }
    }

    int s_loc = 0, q_loc = 0;
#pragma unroll
    for (int j = 0; j < N2; j++)
#pragma unroll
        for (int o = 16; o > 0; o >>= 1)
            acc0[j] += __shfl_xor_sync(0xffffffffu, acc0[j], o);
    if (lane < N2) {
        int v = acc0[lane];
        g_C2[row0 * N2 + lane] = v;
        s_loc += v; q_loc += v * v;
        atomicAdd(&g_hist[lane * HBINS + v + 1024], 1);
    }
#pragma unroll
    for (int j = 0; j < N2; j++)
#pragma unroll
        for (int o = 16; o > 0; o >>= 1)
            acc1[j] += __shfl_xor_sync(0xffffffffu, acc1[j], o);
    if (lane < N2) {
        int v = acc1[lane];
        g_C2[(row0 + 1) * N2 + lane] = v;
        s_loc += v; q_loc += v * v;
        atomicAdd(&g_hist[lane * HBINS + v + 1024], 1);
        atomicAdd(&bsum[lane], s_loc);
        atomicAdd(&bsq [lane], q_loc);   // <= 16 * 1024^2 per block < 2^31
    }
    __syncthreads();
    if (t < N2) {   // spread partials: per-address chain is 16 ops
        const int slot = blockIdx.x & 63;
        atomicAdd(&g_sum2p[slot][t], bsum[t]);
        atomicAdd(&g_sq2p [slot][t], bsq[t]);
    }

    // ---- two-level ticket ----
    __threadfence();
    __syncthreads();
    if (t == 0) {
        s_last = 0;
        const int slot = blockIdx.x & 63;
        if (atomicAdd(&g_t2a[slot], 1) == 15) {
            if (atomicAdd(&g_t2m, 1) == 63) s_last = 1;
        }
    }
    __syncthreads();
    if (!s_last) return;

    // ---- last CTA: slot-reduce bn2 + counts from histogram + tn consts ----
    if (t == 0) { cpn[0] = 0; cpn[1] = 0; }
    if (t < N2) {
        long long s = 0, q = 0;
#pragma unroll
        for (int k = 0; k < 64; k++) { s += g_sum2p[k][t]; q += g_sq2p[k][t]; }
        double mean = (double)s * (1.0 / 16384.0);
        double var  = (double)q * (1.0 / 16384.0) - mean * mean;
        float  sc   = gamma2[t] * (float)(1.0 / sqrt(var + 1e-5));
        sc2[t] = sc;
        sh2[t] = beta2[t] - (float)mean * sc;
        g_scale2[t] = sc;
        g_shift2[t] = sh2[t];
    }
    __syncthreads();

    int pos = 0, neg = 0;
    for (int i = t; i < N2 * HBINS; i += 256) {
        int h = g_hist[i];
        if (h) {
            int j = i / HBINS;
            int v = (i - j * HBINS) - 1024;
            float y = (float)v * sc2[j] + sh2[j];
            int tv = terni(y);
            if (tv > 0)  pos += h;
            if (tv < 0)  neg += h;
        }
    }
#pragma unroll
    for (int o = 16; o > 0; o >>= 1) {
        pos += __shfl_xor_sync(0xffffffffu, pos, o);
        neg += __shfl_xor_sync(0xffffffffu, neg, o);
    }
    if ((t & 31) == 0) { atomicAdd(&cpn[0], pos); atomicAdd(&cpn[1], neg); }
    __syncthreads();
    if (t == 0) {
        const double N = (double)OUT_N;
        double np = (double)cpn[0], nn = (double)cpn[1];
        double mean = (np - nn) / N;
        double var  = (np + nn - N * mean * mean) / (N - 1.0);   // ddof=1
        g_tn_mean = (float)mean;
        g_tn_inv  = (float)(1.0 / sqrt(var + 1e-4));
    }
}

// ------------------------------ final output (pure fp32) --------------------
__global__ void __launch_bounds__(256)
final_kernel(const float* __restrict__ tn_w, const float* __restrict__ tn_b,
             float* __restrict__ out) {
    __shared__ float s_sc[N2], s_sh[N2];
    if (threadIdx.x < N2) {
        s_sc[threadIdx.x] = g_scale2[threadIdx.x];
        s_sh[threadIdx.x] = g_shift2[threadIdx.x];
    }
    __syncthreads();

    int idx = blockIdx.x * 256 + threadIdx.x;
    if (idx >= OUT_N) return;
    int j = idx % N2;
    float y  = (float)g_C2[idx] * s_sc[j] + s_sh[j];
    float tv = (float)terni(y);
    out[idx] = (tv - g_tn_mean) * g_tn_inv * tn_w[0] + tn_b[0];
}

// ------------------------------ launcher ------------------------------------
// 5 launches; gemm2 sits at index 3 (the slot the ncu pass captures).
extern "C" void kernel_launch(void* const* d_in, const int* in_sizes, int n_in,
                              void* d_out, int out_size) {
    const float* x      = (const float*)d_in[0];
    const float* W1     = (const float*)d_in[1];
    const float* gamma1 = (const float*)d_in[2];
    const float* beta1  = (const float*)d_in[3];
    const float* W2     = (const float*)d_in[4];
    const float* gamma2 = (const float*)d_in[5];
    const float* beta2  = (const float*)d_in[6];
    const float* tn_w   = (const float*)d_in[7];
    const float* tn_b   = (const float*)d_in[8];
    float* out = (float*)d_out;

    quant_x_kernel<<<6272, 256>>>(x);                  // 0 (2 float4/thread)
    quant_w_kernel<<<794, 256>>>(W1, W2);              // 1 (+ all zeroing)

    dim3 g1(B_ROWS / 128, N1 / 128);
    gemm1_kernel<<<g1, 256>>>(gamma1, beta1);          // 2 (+ thresholds/W2adj)

    gemm2_kernel<<<B_ROWS / 16, 256>>>(gamma2, beta2); // 3 (+ hist/bn2/tn) <- ncu
    final_kernel<<<(OUT_N + 255) / 256, 256>>>(tn_w, tn_b, out);  // 4
}

// round 17
// speedup vs baseline: 1.0151x; 1.0151x over previous
#include <cuda_runtime.h>
#include <cstdint>

// ---------------------------------------------------------------------------
// QuantTrinaryFCMNIST — Round 16: R15 minus the C2 histogram (the one element
// common to all ~40us gemm2 variants). Counts via separate pass over C2 with
// 64-slot spread partials; final recomputes tn consts per-block (exact).
// All cross-batch stats exact integer sums -> deterministic.
// ---------------------------------------------------------------------------

#define B_ROWS 16384
#define K1     784          // 12 chunks of 64B + 1 tail of 16B
#define N1     1024
#define K2     1024
#define N2     10
#define OUT_N  (B_ROWS * N2)

typedef unsigned int uint;
typedef unsigned long long ull;

// ------------------------- scratch (device globals) ------------------------
__device__ __align__(256) int8_t g_Aq [(size_t)B_ROWS * K1];
__device__ __align__(256) int8_t g_W1q[(size_t)N1 * K1];
__device__ __align__(256) int8_t g_W2q[N2 * K2];
__device__ __align__(256) int8_t g_W2adj[N2 * K2];   // sign-folded W2
__device__ __align__(256) short  g_C1s[(size_t)B_ROWS * N1];
__device__ __align__(16)  short  g_thrH[N1];         // tern thresholds
__device__ __align__(16)  short  g_thrL[N1];
__device__ int    g_C2 [OUT_N];
__device__ int    g_sum1[N1];
__device__ ull    g_sq1 [N1];
__device__ int    g_sum2p[64][N2];     // spread partials (bn2)
__device__ int    g_sq2p [64][N2];
__device__ float  g_scale2[N2], g_shift2[N2];
__device__ int    g_cntp[64][2];       // spread partials (tern counts)
__device__ int    g_t1a[64], g_t1m;    // gemm1 two-level ticket
__device__ int    g_t2a[64], g_t2m;    // gemm2 two-level ticket

// exact: clip(round-half-even(y),-1,1) == (y>0.5)-(y<-0.5) for all floats
__device__ __forceinline__ int terni(float y) {
    return (int)(y > 0.5f) - (int)(y < -0.5f);
}

__device__ __forceinline__ uint smem_u32(const void* p) {
    uint a;
    asm("{ .reg .u64 t; cvta.to.shared.u64 t, %1; cvt.u32.u64 %0, t; }"
        : "=r"(a) : "l"(p));
    return a;
}
#define CP_ASYNC16(dst, src) \
    asm volatile("cp.async.ca.shared.global [%0], [%1], 16;" \
                 :: "r"(dst), "l"(src) : "memory")
#define CP_COMMIT() asm volatile("cp.async.commit_group;" ::: "memory")
#define CP_WAIT0()  asm volatile("cp.async.wait_group 0;" ::: "memory")

// --------------------------- quantize kernels ------------------------------
// tern(2x-1): 2x-1>0.5 <=> x>0.75 ; 2x-1<-0.5 <=> x<0.25. 2 float4/thread.
__global__ void __launch_bounds__(256) quant_x_kernel(const float* __restrict__ x) {
    int i0 = blockIdx.x * 512 + threadIdx.x;
    float4 fa = reinterpret_cast<const float4*>(x)[i0];
    float4 fb = reinterpret_cast<const float4*>(x)[i0 + 256];
    char4 va, vb;
    va.x = (int8_t)((fa.x > 0.75f) - (fa.x < 0.25f));
    va.y = (int8_t)((fa.y > 0.75f) - (fa.y < 0.25f));
    va.z = (int8_t)((fa.z > 0.75f) - (fa.z < 0.25f));
    va.w = (int8_t)((fa.w > 0.75f) - (fa.w < 0.25f));
    vb.x = (int8_t)((fb.x > 0.75f) - (fb.x < 0.25f));
    vb.y = (int8_t)((fb.y > 0.75f) - (fb.y < 0.25f));
    vb.z = (int8_t)((fb.z > 0.75f) - (fb.z < 0.25f));
    vb.w = (int8_t)((fb.w > 0.75f) - (fb.w < 0.25f));
    reinterpret_cast<char4*>(g_Aq)[i0]       = va;
    reinterpret_cast<char4*>(g_Aq)[i0 + 256] = vb;
}

// W1 (784 float4-blocks) + W2 (10 blocks) + all zeroing, one kernel
__global__ void __launch_bounds__(256) quant_w_kernel(const float* __restrict__ w1,
                                                      const float* __restrict__ w2) {
    const int b = blockIdx.x, t = threadIdx.x;
    if (b < 784) {
        int idx = b * 256 + t;
        float4 f = reinterpret_cast<const float4*>(w1)[idx];
        char4 v;
        v.x = (int8_t)terni(f.x);
        v.y = (int8_t)terni(f.y);
        v.z = (int8_t)terni(f.z);
        v.w = (int8_t)terni(f.w);
        reinterpret_cast<char4*>(g_W1q)[idx] = v;
    } else {
        int idx = (b - 784) * 256 + t;
        if (idx < N2 * K2 / 4) {
            float4 f = reinterpret_cast<const float4*>(w2)[idx];
            char4 v;
            v.x = (int8_t)terni(f.x);
            v.y = (int8_t)terni(f.y);
            v.z = (int8_t)terni(f.z);
            v.w = (int8_t)terni(f.w);
            reinterpret_cast<char4*>(g_W2q)[idx] = v;
        }
    }
    if (b == 100) {
        for (int j = t; j < N1; j += 256) g_sum1[j] = 0;
    } else if (b == 101) {
        for (int j = t; j < N1; j += 256) g_sq1[j] = 0ull;
    } else if (b == 102) {
        for (int i = t; i < 64 * N2; i += 256) {
            (&g_sum2p[0][0])[i] = 0;
            (&g_sq2p[0][0])[i]  = 0;
        }
        if (t < 128) (&g_cntp[0][0])[t] = 0;
        if (t >= 128 && t < 192) { g_t1a[t - 128] = 0; g_t2a[t - 128] = 0; }
        if (t == 192) { g_t1m = 0; g_t2m = 0; }
    }
}

// ------------------------------- GEMM1 (dp4a) -------------------------------
// Core UNCHANGED (at the rt=2 dp4a roofline). Tile 128x128, BK=64 + 16B tail,
// 256 threads, 8x8/thread, double-buffered, one sync/chunk.
// Last CTA: per-column integer tern thresholds (bit-exact binary search over
// the float fma expression) + sign-folded W2adj.
#define SP 132

__global__ void __launch_bounds__(256, 2)
gemm1_kernel(const float* __restrict__ gamma1, const float* __restrict__ beta1) {
    __shared__ __align__(16) uint As[2][16][SP];
    __shared__ __align__(16) uint Bs[2][16][SP];
    __shared__ int s_sum[128];
    __shared__ int s_sq [128];
    __shared__ int s_last;
    __shared__ char s_flip[N1];

    const int t  = threadIdx.x;
    const int ty = t >> 4, tx = t & 15;
    const int m0 = blockIdx.x * 128;
    const int n0 = blockIdx.y * 128;

    int acc[8][8];
#pragma unroll
    for (int i = 0; i < 8; i++)
#pragma unroll
        for (int j = 0; j < 8; j++) acc[i][j] = 0;

    const int prow = t >> 2, pseg = t & 3;
    const int8_t* Ag0 = g_Aq  + (size_t)(m0 + prow)      * K1 + pseg * 16;
    const int8_t* Ag1 = g_Aq  + (size_t)(m0 + prow + 64) * K1 + pseg * 16;
    const int8_t* Bg0 = g_W1q + (size_t)(n0 + prow)      * K1 + pseg * 16;
    const int8_t* Bg1 = g_W1q + (size_t)(n0 + prow + 64) * K1 + pseg * 16;

    uint4 ra0, ra1, rb0, rb1;

    ra0 = *reinterpret_cast<const uint4*>(Ag0);
    ra1 = *reinterpret_cast<const uint4*>(Ag1);
    rb0 = *reinterpret_cast<const uint4*>(Bg0);
    rb1 = *reinterpret_cast<const uint4*>(Bg1);
#pragma unroll
    for (int w = 0; w < 4; w++) {
        As[0][pseg * 4 + w][prow]      = (&ra0.x)[w];
        As[0][pseg * 4 + w][prow + 64] = (&ra1.x)[w];
        Bs[0][pseg * 4 + w][prow]      = (&rb0.x)[w];
        Bs[0][pseg * 4 + w][prow + 64] = (&rb1.x)[w];
    }
    __syncthreads();

    for (int kc = 0; kc < 12; kc++) {
        const int buf = kc & 1;
        const bool next_full = (kc + 1 < 12);
        if (next_full) {
            ra0 = *reinterpret_cast<const uint4*>(Ag0 + (kc + 1) * 64);
            ra1 = *reinterpret_cast<const uint4*>(Ag1 + (kc + 1) * 64);
            rb0 = *reinterpret_cast<const uint4*>(Bg0 + (kc + 1) * 64);
            rb1 = *reinterpret_cast<const uint4*>(Bg1 + (kc + 1) * 64);
        } else if (pseg == 0) {          // tail: bytes 768..783
            ra0 = *reinterpret_cast<const uint4*>(Ag0 + 768);
            ra1 = *reinterpret_cast<const uint4*>(Ag1 + 768);
            rb0 = *reinterpret_cast<const uint4*>(Bg0 + 768);
            rb1 = *reinterpret_cast<const uint4*>(Bg1 + 768);
        }

#pragma unroll
        for (int kk = 0; kk < 16; kk++) {
            uint4 a0 = *reinterpret_cast<const uint4*>(&As[buf][kk][ty * 8]);
            uint4 a1 = *reinterpret_cast<const uint4*>(&As[buf][kk][ty * 8 + 4]);
            uint4 b0 = *reinterpret_cast<const uint4*>(&Bs[buf][kk][tx * 8]);
            uint4 b1 = *reinterpret_cast<const uint4*>(&Bs[buf][kk][tx * 8 + 4]);
            int a[8] = {(int)a0.x, (int)a0.y, (int)a0.z, (int)a0.w,
                        (int)a1.x, (int)a1.y, (int)a1.z, (int)a1.w};
            int b[8] = {(int)b0.x, (int)b0.y, (int)b0.z, (int)b0.w,
                        (int)b1.x, (int)b1.y, (int)b1.z, (int)b1.w};
#pragma unroll
            for (int i = 0; i < 8; i++)
#pragma unroll
                for (int j = 0; j < 8; j++)
                    acc[i][j] = __dp4a(a[i], b[j], acc[i][j]);
        }

        const int nb = buf ^ 1;
        if (next_full) {
#pragma unroll
            for (int w = 0; w < 4; w++) {
                As[nb][pseg * 4 + w][prow]      = (&ra0.x)[w];
                As[nb][pseg * 4 + w][prow + 64] = (&ra1.x)[w];
                Bs[nb][pseg * 4 + w][prow]      = (&rb0.x)[w];
                Bs[nb][pseg * 4 + w][prow + 64] = (&rb1.x)[w];
            }
        } else if (pseg == 0) {
#pragma unroll
            for (int w = 0; w < 4; w++) {
                As[nb][w][prow]      = (&ra0.x)[w];
                As[nb][w][prow + 64] = (&ra1.x)[w];
                Bs[nb][w][prow]      = (&rb0.x)[w];
                Bs[nb][w][prow + 64] = (&rb1.x)[w];
            }
        }
        __syncthreads();
    }

    // tail chunk (4 kwords) sits in buffer 0
#pragma unroll
    for (int kk = 0; kk < 4; kk++) {
        uint4 a0 = *reinterpret_cast<const uint4*>(&As[0][kk][ty * 8]);
        uint4 a1 = *reinterpret_cast<const uint4*>(&As[0][kk][ty * 8 + 4]);
        uint4 b0 = *reinterpret_cast<const uint4*>(&Bs[0][kk][tx * 8]);
        uint4 b1 = *reinterpret_cast<const uint4*>(&Bs[0][kk][tx * 8 + 4]);
        int a[8] = {(int)a0.x, (int)a0.y, (int)a0.z, (int)a0.w,
                    (int)a1.x, (int)a1.y, (int)a1.z, (int)a1.w};
        int b[8] = {(int)b0.x, (int)b0.y, (int)b0.z, (int)b0.w,
                    (int)b1.x, (int)b1.y, (int)b1.z, (int)b1.w};
#pragma unroll
        for (int i = 0; i < 8; i++)
#pragma unroll
            for (int j = 0; j < 8; j++)
                acc[i][j] = __dp4a(a[i], b[j], acc[i][j]);
    }

    // ------------- epilogue: int16 C1 + fused exact BN1 stats -------------
    if (t < 128) { s_sum[t] = 0; s_sq[t] = 0; }
    __syncthreads();

#pragma unroll
    for (int i = 0; i < 8; i++) {
        const int row = m0 + ty * 8 + i;
        uint u0 = ((uint)acc[i][0] & 0xffffu) | ((uint)acc[i][1] << 16);
        uint u1 = ((uint)acc[i][2] & 0xffffu) | ((uint)acc[i][3] << 16);
        uint u2 = ((uint)acc[i][4] & 0xffffu) | ((uint)acc[i][5] << 16);
        uint u3 = ((uint)acc[i][6] & 0xffffu) | ((uint)acc[i][7] << 16);
        *reinterpret_cast<uint4*>((char*)g_C1s + (size_t)row * 2048 + (n0 + tx * 8) * 2) =
            make_uint4(u0, u1, u2, u3);
    }

#pragma unroll
    for (int j = 0; j < 8; j++) {
        int s = 0, q = 0;
#pragma unroll
        for (int i = 0; i < 8; i++) { s += acc[i][j]; q += acc[i][j] * acc[i][j]; }
        atomicAdd(&s_sum[tx * 8 + j], s);
        atomicAdd(&s_sq [tx * 8 + j], q);
    }
    __syncthreads();
    if (t < 128) {
        atomicAdd(&g_sum1[n0 + t], s_sum[t]);
        atomicAdd(&g_sq1 [n0 + t], (ull)(uint)s_sq[t]);
    }

    // ---- two-level ticket; last CTA computes thresholds + W2adj once ----
    __threadfence();
    __syncthreads();
    if (t == 0) {
        s_last = 0;
        const int slot = (blockIdx.y * 128 + blockIdx.x) & 63;
        if (atomicAdd(&g_t1a[slot], 1) == 15) {
            if (atomicAdd(&g_t1m, 1) == 63) s_last = 1;
        }
    }
    __syncthreads();
    if (s_last) {
        for (int j = t; j < N1; j += 256) {
            double mean = (double)g_sum1[j] * (1.0 / 16384.0);
            double var  = (double)g_sq1[j]  * (1.0 / 16384.0) - mean * mean;
            float  sc   = gamma1[j] * (float)(1.0 / sqrt(var + 1e-5));
            float  sf   = beta1[j] - (float)mean * sc;
            float  as   = sc;
            int flip = 0;
            if (as < 0.f) { as = -as; flip = 1; }
            int hi, lo;
            if (as == 0.f) {
                int tv = (sf > 0.5f) - (sf < -0.5f);
                if (tv > 0)       { hi = -1000; lo = -1000; }
                else if (tv == 0) { hi =  1000; lo = -1000; }
                else              { hi =  1000; lo =  1000; }
                flip = 0;
            } else {
                // terni(fmaf(d,as,sf)) over d in [-784,784], monotone in d
                int a = -785, b = 784;          // hi: max d with y <= 0.5f
                while (a < b) {
                    int m = (a + b + 1) >> 1;
                    if (fmaf((float)m, as, sf) <= 0.5f) a = m; else b = m - 1;
                }
                int HI = a;
                a = -784; b = 785;              // lo: min d with y >= -0.5f
                while (a < b) {
                    int m = (a + b) >> 1;
                    if (fmaf((float)m, as, sf) >= -0.5f) b = m; else a = m + 1;
                }
                int LO = a;
                if (!flip) { hi = HI; lo = LO; }
                else       { hi = -LO; lo = -HI; }   // tern = -[(c>hi)-(c<lo)]
            }
            g_thrH[j] = (short)hi;
            g_thrL[j] = (short)lo;
            s_flip[j] = (char)flip;
        }
        __syncthreads();
        for (int i = t; i < N2 * K2; i += 256) {   // sign-folded W2
            int k = i & 1023;
            int8_t w = g_W2q[i];
            g_W2adj[i] = s_flip[k] ? (int8_t)(-w) : w;
        }
    }
}

// ------------------------------- GEMM2 --------------------------------------
// Fused: t = (c>hi)-(c<lo) integer ternarize; C2 = t @ W2adj^T;
// BN2 stats via 64-slot spread partials. All inner-loop operands in smem.
// NO histogram. Two-level ticket; last CTA: slot-reduce bn2 params only.
__global__ void __launch_bounds__(256, 3)
gemm2_kernel(const float* __restrict__ gamma2, const float* __restrict__ beta2) {
    __shared__ __align__(16) short c1s[16 * K2];     // 32KB
    __shared__ __align__(16) uint2 w2v[N2 * 128];    // 10KB, [j][idx]
    __shared__ __align__(16) short thrH[K2];         // 2KB
    __shared__ __align__(16) short thrL[K2];         // 2KB
    __shared__ int   bsum[N2], bsq[N2];
    __shared__ int   s_last;

    const int t = threadIdx.x;

    // ---- stage C1 tile + W2adj + thresholds via cp.async ----
    {
        const uint sc1 = smem_u32(c1s);
        const char* gsrc = (const char*)(g_C1s + (size_t)blockIdx.x * 16 * K2);
#pragma unroll
        for (int i = 0; i < 8; i++) {               // 2048 x 16B = 32KB
            int off = (i * 256 + t) * 16;
            CP_ASYNC16(sc1 + off, gsrc + off);
        }
        const uint sw = smem_u32(w2v);
        const char* gw = (const char*)g_W2adj;
        for (int i = t; i < 640; i += 256)           // 10KB
            CP_ASYNC16(sw + i * 16, gw + i * 16);
        if (t < 128)
            CP_ASYNC16(smem_u32(thrH) + t * 16, (const char*)g_thrH + t * 16);
        else
            CP_ASYNC16(smem_u32(thrL) + (t - 128) * 16,
                       (const char*)g_thrL + (t - 128) * 16);
        CP_COMMIT();
    }
    if (t < N2) { bsum[t] = 0; bsq[t] = 0; }
    CP_WAIT0();
    __syncthreads();

    const int warp = t >> 5, lane = t & 31;
    const int row0 = blockIdx.x * 16 + warp * 2;
    const int rloc = warp * 2;

    int acc0[N2], acc1[N2];
#pragma unroll
    for (int j = 0; j < N2; j++) { acc0[j] = 0; acc1[j] = 0; }

#pragma unroll
    for (int it = 0; it < 4; it++) {
        const int idx = it * 32 + lane;
        // row-invariant operands, all from smem
        short4 h0 = *reinterpret_cast<const short4*>(&thrH[idx * 8]);
        short4 h1 = *reinterpret_cast<const short4*>(&thrH[idx * 8 + 4]);
        short4 l0 = *reinterpret_cast<const short4*>(&thrL[idx * 8]);
        short4 l1 = *reinterpret_cast<const short4*>(&thrL[idx * 8 + 4]);
        uint2 w[N2];
#pragma unroll
        for (int j = 0; j < N2; j++) w[j] = w2v[j * 128 + idx];

#pragma unroll
        for (int r = 0; r < 2; r++) {
            const short4* cp = reinterpret_cast<const short4*>(
                c1s + (rloc + r) * K2 + idx * 8);
            short4 c0 = cp[0];
            short4 c1 = cp[1];
            int t0 = (c0.x > h0.x) - (c0.x < l0.x);
            int t1 = (c0.y > h0.y) - (c0.y < l0.y);
            int t2 = (c0.z > h0.z) - (c0.z < l0.z);
            int t3 = (c0.w > h0.w) - (c0.w < l0.w);
            int t4 = (c1.x > h1.x) - (c1.x < l1.x);
            int t5 = (c1.y > h1.y) - (c1.y < l1.y);
            int t6 = (c1.z > h1.z) - (c1.z < l1.z);
            int t7 = (c1.w > h1.w) - (c1.w < l1.w);
            uint p0 = (uint)(t0 & 0xff) | ((uint)(t1 & 0xff) << 8) |
                      ((uint)(t2 & 0xff) << 16) | ((uint)(t3 & 0xff) << 24);
            uint p1 = (uint)(t4 & 0xff) | ((uint)(t5 & 0xff) << 8) |
                      ((uint)(t6 & 0xff) << 16) | ((uint)(t7 & 0xff) << 24);
            if (r == 0) {
#pragma unroll
                for (int j = 0; j < N2; j++) {
                    acc0[j] = __dp4a((int)p0, (int)w[j].x, acc0[j]);
                    acc0[j] = __dp4a((int)p1, (int)w[j].y, acc0[j]);
                }
            } else {
#pragma unroll
                for (int j = 0; j < N2; j++) {
                    acc1[j] = __dp4a((int)p0, (int)w[j].x, acc1[j]);
                    acc1[j] = __dp4a((int)p1, (int)w[j].y, acc1[j]);
                }
            }
        }
    }

    int s_loc = 0, q_loc = 0;
#pragma unroll
    for (int j = 0; j < N2; j++)
#pragma unroll
        for (int o = 16; o > 0; o >>= 1)
            acc0[j] += __shfl_xor_sync(0xffffffffu, acc0[j], o);
    if (lane < N2) {
        int v = acc0[lane];
        g_C2[row0 * N2 + lane] = v;
        s_loc += v; q_loc += v * v;
    }
#pragma unroll
    for (int j = 0; j < N2; j++)
#pragma unroll
        for (int o = 16; o > 0; o >>= 1)
            acc1[j] += __shfl_xor_sync(0xffffffffu, acc1[j], o);
    if (lane < N2) {
        int v = acc1[lane];
        g_C2[(row0 + 1) * N2 + lane] = v;
        s_loc += v; q_loc += v * v;
        atomicAdd(&bsum[lane], s_loc);
        atomicAdd(&bsq [lane], q_loc);   // <= 16 * 1024^2 per block < 2^31
    }
    __syncthreads();
    if (t < N2) {   // spread partials: per-address chain is 16 ops
        const int slot = blockIdx.x & 63;
        atomicAdd(&g_sum2p[slot][t], bsum[t]);
        atomicAdd(&g_sq2p [slot][t], bsq[t]);
    }

    // ---- two-level ticket ----
    __threadfence();
    __syncthreads();
    if (t == 0) {
        s_last = 0;
        const int slot = blockIdx.x & 63;
        if (atomicAdd(&g_t2a[slot], 1) == 15) {
            if (atomicAdd(&g_t2m, 1) == 63) s_last = 1;
        }
    }
    __syncthreads();
    if (!s_last) return;

    // ---- last CTA: slot-reduce bn2 params only ----
    if (t < N2) {
        long long s = 0, q = 0;
#pragma unroll
        for (int k = 0; k < 64; k++) { s += g_sum2p[k][t]; q += g_sq2p[k][t]; }
        double mean = (double)s * (1.0 / 16384.0);
        double var  = (double)q * (1.0 / 16384.0) - mean * mean;
        float  sc   = gamma2[t] * (float)(1.0 / sqrt(var + 1e-5));
        g_scale2[t] = sc;
        g_shift2[t] = beta2[t] - (float)mean * sc;
    }
}

// --------------------- count pass: tern(+1/-1) totals ------------------------
__global__ void __launch_bounds__(256)
count_kernel() {
    __shared__ float s_sc[N2], s_sh[N2];
    __shared__ int s[2];
    if (threadIdx.x < N2) {
        s_sc[threadIdx.x] = g_scale2[threadIdx.x];
        s_sh[threadIdx.x] = g_shift2[threadIdx.x];
    }
    if (threadIdx.x == 32) { s[0] = 0; s[1] = 0; }
    __syncthreads();

    int idx = blockIdx.x * 256 + threadIdx.x;
    int pos = 0, neg = 0;
    if (idx < OUT_N) {
        int j = idx % N2;
        float y = (float)g_C2[idx] * s_sc[j] + s_sh[j];
        int tv = terni(y);
        pos = tv > 0;
        neg = tv < 0;
    }
#pragma unroll
    for (int o = 16; o > 0; o >>= 1) {
        pos += __shfl_xor_sync(0xffffffffu, pos, o);
        neg += __shfl_xor_sync(0xffffffffu, neg, o);
    }
    if ((threadIdx.x & 31) == 0) { atomicAdd(&s[0], pos); atomicAdd(&s[1], neg); }
    __syncthreads();
    if (threadIdx.x == 0) {
        const int slot = blockIdx.x & 63;
        atomicAdd(&g_cntp[slot][0], s[0]);
        atomicAdd(&g_cntp[slot][1], s[1]);
    }
}

// ------------------------------ final output --------------------------------
// tn consts recomputed per-block from the 64 partial slots (identical in
// every block -> deterministic); outputs pure fp32.
__global__ void __launch_bounds__(256)
final_kernel(const float* __restrict__ tn_w, const float* __restrict__ tn_b,
             float* __restrict__ out) {
    __shared__ float s_sc[N2], s_sh[N2];
    __shared__ float s_m, s_i;
    if (threadIdx.x < N2) {
        s_sc[threadIdx.x] = g_scale2[threadIdx.x];
        s_sh[threadIdx.x] = g_shift2[threadIdx.x];
    }
    if (threadIdx.x == 32) {
        int np = 0, nn = 0;
#pragma unroll
        for (int k = 0; k < 64; k++) { np += g_cntp[k][0]; nn += g_cntp[k][1]; }
        const double N = (double)OUT_N;
        double mean = ((double)np - (double)nn) / N;
        double var  = ((double)np + (double)nn - N * mean * mean) / (N - 1.0);
        s_m = (float)mean;
        s_i = (float)(1.0 / sqrt(var + 1e-4));
    }
    __syncthreads();

    int idx = blockIdx.x * 256 + threadIdx.x;
    if (idx >= OUT_N) return;
    int j = idx % N2;
    float y  = (float)g_C2[idx] * s_sc[j] + s_sh[j];
    float tv = (float)terni(y);
    out[idx] = (tv - s_m) * s_i * tn_w[0] + tn_b[0];
}

// ------------------------------ launcher ------------------------------------
// 6 launches; gemm2 sits at index 3 (the slot the ncu pass captures).
extern "C" void kernel_launch(void* const* d_in, const int* in_sizes, int n_in,
                              void* d_out, int out_size) {
    const float* x      = (const float*)d_in[0];
    const float* W1     = (const float*)d_in[1];
    const float* gamma1 = (const float*)d_in[2];
    const float* beta1  = (const float*)d_in[3];
    const float* W2     = (const float*)d_in[4];
    const float* gamma2 = (const float*)d_in[5];
    const float* beta2  = (const float*)d_in[6];
    const float* tn_w   = (const float*)d_in[7];
    const float* tn_b   = (const float*)d_in[8];
    float* out = (float*)d_out;

    quant_x_kernel<<<6272, 256>>>(x);                  // 0 (2 float4/thread)
    quant_w_kernel<<<794, 256>>>(W1, W2);              // 1 (+ all zeroing)

    dim3 g1(B_ROWS / 128, N1 / 128);
    gemm1_kernel<<<g1, 256>>>(gamma1, beta1);          // 2 (+ thresholds/W2adj)

    gemm2_kernel<<<B_ROWS / 16, 256>>>(gamma2, beta2); // 3 (NO hist)  <- ncu
    count_kernel<<<(OUT_N + 255) / 256, 256>>>();      // 4
    final_kernel<<<(OUT_N + 255) / 256, 256>>>(tn_w, tn_b, out);  // 5
}